// round 6
// baseline (speedup 1.0000x reference)
#include <cuda_runtime.h>

#define B_ 32
#define S_ 4
#define L_ 64
#define C_ 32
#define H_ 4
#define D_ 8
#define CP_ 16

typedef unsigned long long u64;

__device__ __forceinline__ u64 fma2(u64 a, u64 b, u64 c){
    u64 d; asm("fma.rn.f32x2 %0,%1,%2,%3;" : "=l"(d) : "l"(a),"l"(b),"l"(c)); return d;
}
__device__ __forceinline__ u64 mul2(u64 a, u64 b){
    u64 d; asm("mul.rn.f32x2 %0,%1,%2;" : "=l"(d) : "l"(a),"l"(b)); return d;
}
__device__ __forceinline__ u64 add2(u64 a, u64 b){
    u64 d; asm("add.rn.f32x2 %0,%1,%2;" : "=l"(d) : "l"(a),"l"(b)); return d;
}
__device__ __forceinline__ u64 pack2(float lo, float hi){
    u64 d; asm("mov.b64 %0,{%1,%2};" : "=l"(d) : "f"(lo),"f"(hi)); return d;
}
__device__ __forceinline__ float2 unpack2(u64 v){
    float x,y; asm("mov.b64 {%0,%1},%2;" : "=f"(x),"=f"(y) : "l"(v)); return make_float2(x,y);
}

__device__ float g_xbuf[B_*S_*L_*C_];
__device__ float g_mbuf[B_*L_*C_];
__device__ float g_nrm[B_*L_];
__device__ float g_wibuf[B_*L_*CP_*C_];

// row swizzles (key multiple of 4 -> float4 alignment preserved)
__device__ __forceinline__ int xi(int r, int c){
    const int key = (((r>>2)&7) ^ (((r>>5)&1)<<2)) << 2;
    return r*36 + (c ^ key);
}
__device__ __forceinline__ int swz(int r, int c){
    return r*36 + (c ^ (((r>>2)&7)<<2));
}

// ---------------------------------------------------------------------------
// Kernel A: grid = (b, s, half) = 256 blocks, 512 threads.
// Each block owns l in [32*half, 32*half+32); K/V computed for all 64 rows.
// smem floats:
//   XS@0 (64x36)  QS@2304 (32x36, own l)  KS@3456 (64x36)  VS@5760 (64x36)
//   WQ@8064 WK@9120 WV@10176 WO@11232 (32x33 each)
//   BK@12288 (32x66, own l rows)  GW@14400(256) GB@14656(32)
//   total 14688 floats = 58752 B  (2 blocks/SM)
// ---------------------------------------------------------------------------
#define QSOFF 2304
#define KSOFF 3456
#define VSOFF 5760
#define KA_SMEM (14688*4)
#define BK2(l,m) sm[12288 + (l)*66 + (m)]

__global__ void __launch_bounds__(512) kA(
    const float* __restrict__ chip0, const float* __restrict__ chip1,
    const float* __restrict__ chip2, const float* __restrict__ chip3,
    const float* __restrict__ bulk,
    const float* __restrict__ we_w, const float* __restrict__ we_b,
    const float* __restrict__ pos,
    const float* __restrict__ mn_g, const float* __restrict__ mn_b,
    const float* __restrict__ wq, const float* __restrict__ bq,
    const float* __restrict__ wk, const float* __restrict__ bk,
    const float* __restrict__ wv, const float* __restrict__ bv,
    const float* __restrict__ wo, const float* __restrict__ bo,
    const float* __restrict__ an_g, const float* __restrict__ an_b,
    const float* __restrict__ conv_w, const float* __restrict__ conv_b,
    const float* __restrict__ gate_w, const float* __restrict__ gate_b)
{
    extern __shared__ float sm[];
    const int t = threadIdx.x;
    const int b = blockIdx.x >> 3, s = (blockIdx.x >> 1) & 3, half = blockIdx.x & 1;
    const int lbase0 = half * 32;
    const float* chip = (s==0)?chip0:(s==1)?chip1:(s==2)?chip2:chip3;

    for (int idx = t; idx < C_*C_; idx += 512) {
        const int r = idx >> 5, c = idx & 31;
        sm[8064  + r*33 + c] = wq[idx];
        sm[9120  + r*33 + c] = wk[idx];
        sm[10176 + r*33 + c] = wv[idx];
        sm[11232 + r*33 + c] = wo[idx];
    }
    for (int idx = t; idx < 32*64; idx += 512) {
        const int r = idx >> 6, m = idx & 63;
        BK2(r,m) = bulk[b*L_*L_ + (lbase0 + r)*L_ + m];
    }
    if (t < 256) sm[14400 + t] = gate_w[t];
    if (t >= 256 && t < 288) sm[14656 + t - 256] = gate_b[t - 256];

    // phase 1: msa + pos, LN(mn), ALL 64 rows. 8 threads/row, 4 c each.
    {
        const int l = t >> 3, oct = t & 7, c0 = oct*4;
        const float sig = chip[b*L_ + l];
        float v[4]; float s1 = 0.f, s2 = 0.f;
        #pragma unroll
        for (int j = 0; j < 4; j++) {
            const int c = c0 + j;
            const float val = fmaf(sig, we_w[c], we_b[c]) + pos[l*C_ + c];
            v[j] = val; s1 += val; s2 += val*val;
        }
        #pragma unroll
        for (int o = 1; o < 8; o <<= 1) {
            s1 += __shfl_xor_sync(0xffffffffu, s1, o);
            s2 += __shfl_xor_sync(0xffffffffu, s2, o);
        }
        const float mean = s1*(1.f/C_);
        const float rstd = rsqrtf(s2*(1.f/C_) - mean*mean + 1e-5f);
        #pragma unroll
        for (int j = 0; j < 4; j++) {
            const int c = c0 + j;
            sm[xi(l,c)] = (v[j]-mean)*rstd*mn_g[c] + mn_b[c];
        }
    }
    __syncthreads();

    // phase 2: K,V for ALL 64 rows (warp -> 4 rows) + Q for own 32 (warp -> 2).
    {
        const int co = t & 31, w = t >> 5;
        {   // K,V: rows 4w..4w+3
            const int rb = w * 4;
            float ak[4], av[4];
            const float ibk = bk[co], ibv = bv[co];
            #pragma unroll
            for (int k = 0; k < 4; k++) { ak[k]=ibk; av[k]=ibv; }
            #pragma unroll 8
            for (int c = 0; c < C_; c++) {
                const float wkv = sm[9120  + co*33 + c];
                const float wvv = sm[10176 + co*33 + c];
                #pragma unroll
                for (int k = 0; k < 4; k++) {
                    const float xv = sm[xi(rb+k, c)];
                    ak[k] += xv*wkv; av[k] += xv*wvv;
                }
            }
            #pragma unroll
            for (int k = 0; k < 4; k++) {
                sm[KSOFF + xi(rb+k,co)] = ak[k];
                sm[VSOFF + xi(rb+k,co)] = av[k];
            }
        }
        {   // Q: own local rows 2w, 2w+1
            const int rb = w * 2;
            float aq[2];
            const float ibq = bq[co];
            aq[0] = ibq; aq[1] = ibq;
            #pragma unroll 8
            for (int c = 0; c < C_; c++) {
                const float wqv = sm[8064 + co*33 + c];
                #pragma unroll
                for (int k = 0; k < 2; k++)
                    aq[k] += sm[xi(lbase0 + rb+k, c)]*wqv;
            }
            #pragma unroll
            for (int k = 0; k < 2; k++)
                sm[QSOFF + xi(rb+k,co)] = aq[k];
        }
    }
    __syncthreads();

    // phase 3: attention for own 32 l. thread = (h, ll, quarter); m = 4mm+q.
    {
        const int h = t >> 7, rem = t & 127;
        const int ll = rem >> 2, quarter = rem & 3;
        const int hc = h*D_;
        const float rsd = 0.35355339059327373f;

        ulonglong2 qa = *reinterpret_cast<const ulonglong2*>(&sm[QSOFF + xi(ll,hc)]);
        ulonglong2 qb = *reinterpret_cast<const ulonglong2*>(&sm[QSOFF + xi(ll,hc+4)]);
        const u64 rsd2 = pack2(rsd, rsd);
        qa.x = mul2(qa.x, rsd2); qa.y = mul2(qa.y, rsd2);
        qb.x = mul2(qb.x, rsd2); qb.y = mul2(qb.y, rsd2);
        const float cw = conv_w[h], cb = conv_b[h];

        float Z = 0.f;
        u64 A0 = 0ull, A1 = 0ull, A2 = 0ull, A3 = 0ull;

        #pragma unroll 4
        for (int mm = 0; mm < 16; mm++) {
            const int m = mm*4 + quarter;
            const ulonglong2 ka = *reinterpret_cast<const ulonglong2*>(&sm[KSOFF + xi(m,hc)]);
            const ulonglong2 kb = *reinterpret_cast<const ulonglong2*>(&sm[KSOFF + xi(m,hc+4)]);
            u64 u = mul2(qa.x, ka.x);
            u = fma2(qa.y, ka.y, u);
            u = fma2(qb.x, kb.x, u);
            u = fma2(qb.y, kb.y, u);
            const float2 uf = unpack2(u);
            const float sc = uf.x + uf.y + fmaf(BK2(ll,m), cw, cb);
            const float p = __expf(sc);
            Z += p;
            const u64 pp = pack2(p, p);
            const ulonglong2 va = *reinterpret_cast<const ulonglong2*>(&sm[VSOFF + xi(m,hc)]);
            const ulonglong2 vb = *reinterpret_cast<const ulonglong2*>(&sm[VSOFF + xi(m,hc+4)]);
            A0 = fma2(pp, va.x, A0); A1 = fma2(pp, va.y, A1);
            A2 = fma2(pp, vb.x, A2); A3 = fma2(pp, vb.y, A3);
        }
        #pragma unroll
        for (int o = 1; o < 4; o <<= 1) {
            Z  += __shfl_xor_sync(0xffffffffu, Z, o);
            A0 = add2(A0, __shfl_xor_sync(0xffffffffu, A0, o));
            A1 = add2(A1, __shfl_xor_sync(0xffffffffu, A1, o));
            A2 = add2(A2, __shfl_xor_sync(0xffffffffu, A2, o));
            A3 = add2(A3, __shfl_xor_sync(0xffffffffu, A3, o));
        }

        __syncthreads();
        if (quarter == 0) {
            const float inv = 1.f/Z;
            const float2 f0 = unpack2(A0), f1 = unpack2(A1), f2 = unpack2(A2), f3 = unpack2(A3);
            float o[D_];
            o[0]=f0.x*inv; o[1]=f0.y*inv; o[2]=f1.x*inv; o[3]=f1.y*inv;
            o[4]=f2.x*inv; o[5]=f2.y*inv; o[6]=f3.x*inv; o[7]=f3.y*inv;
            float4 r0, r1;
            #pragma unroll
            for (int d = 0; d < D_; d++) {
                float g = sm[14656 + hc + d];
                #pragma unroll
                for (int dd = 0; dd < D_; dd++)
                    g += sm[14400 + h*D_*D_ + d*D_ + dd]*o[dd];
                ((d < 4) ? (&r0.x) : (&r1.x))[d & 3] = o[d] / (1.f + __expf(-g));
            }
            *reinterpret_cast<float4*>(&sm[QSOFF + xi(ll,hc)])   = r0;
            *reinterpret_cast<float4*>(&sm[QSOFF + xi(ll,hc+4)]) = r1;
        }
    }
    __syncthreads();

    // phase 4a: wo + residual -> KS (own 32 local rows; warp -> 2 rows)
    {
        const int co = t & 31, rb = (t >> 5) * 2;
        float acc[2];
        const float ib = bo[co];
        acc[0] = ib; acc[1] = ib;
        #pragma unroll 8
        for (int c = 0; c < C_; c++) {
            const float w = sm[11232 + co*33 + c];
            #pragma unroll
            for (int k = 0; k < 2; k++) acc[k] += sm[QSOFF + xi(rb+k, c)]*w;
        }
        #pragma unroll
        for (int k = 0; k < 2; k++)
            sm[KSOFF + xi(rb+k, co)] = sm[xi(lbase0 + rb+k, co)] + acc[k];
    }
    __syncthreads();

    // phase 4b: LN(an) -> g_xbuf. own 32 rows, 16 threads/row, 2 c each.
    {
        const int ll = t >> 4, q = t & 15, c0 = q*2;
        const float v0 = sm[KSOFF + xi(ll, c0)];
        const float v1 = sm[KSOFF + xi(ll, c0+1)];
        float s1 = v0 + v1, s2 = v0*v0 + v1*v1;
        #pragma unroll
        for (int o = 1; o < 16; o <<= 1) {
            s1 += __shfl_xor_sync(0xffffffffu, s1, o);
            s2 += __shfl_xor_sync(0xffffffffu, s2, o);
        }
        const float mean = s1*(1.f/C_);
        const float rstd = rsqrtf(s2*(1.f/C_) - mean*mean + 1e-5f);
        float2 r;
        r.x = (v0-mean)*rstd*an_g[c0]   + an_b[c0];
        r.y = (v1-mean)*rstd*an_g[c0+1] + an_b[c0+1];
        *reinterpret_cast<float2*>(&g_xbuf[((b*S_ + s)*L_ + lbase0 + ll)*C_ + c0]) = r;
    }
}

// ---------------------------------------------------------------------------
// Kernel W: fused max-over-tracks + wi projection + (p==0) m/nrm emission.
// 512 threads; thread = (ig of 4 i's, d).
// ---------------------------------------------------------------------------
__global__ void __launch_bounds__(512) kW(const float* __restrict__ pp_w) {
    __shared__ float ms[L_][C_+1];
    __shared__ float pw[C_][C_+1];
    const int t = threadIdx.x;
    const int b = blockIdx.x >> 4, p = blockIdx.x & 15;
    const float* xb = g_xbuf + b*S_*L_*C_;

    for (int idx = t; idx < L_*C_; idx += 512) {
        float m = fmaxf(fmaxf(xb[idx], xb[2048+idx]),
                        fmaxf(xb[4096+idx], xb[6144+idx]));
        ms[idx>>5][idx&31] = m;
        if (p == 0) g_mbuf[b*L_*C_ + idx] = m;
    }
    for (int idx = t; idx < C_*C_; idx += 512)
        pw[idx>>5][idx&31] = pp_w[p*C_*C_ + idx];
    __syncthreads();

    if (p == 0 && t < L_) {
        float ssum = 0.f;
        #pragma unroll
        for (int c = 0; c < C_; c++) { const float v = ms[t][c]; ssum += v*v; }
        g_nrm[b*L_ + t] = sqrtf(ssum);
    }

    const int d = t & 31, ig = t >> 5;     // 16 groups x 4 i's
    float acc[4];
    #pragma unroll
    for (int k = 0; k < 4; k++) acc[k] = 0.f;
    #pragma unroll 8
    for (int c = 0; c < C_; c++) {
        const float w = pw[c][d];
        #pragma unroll
        for (int k = 0; k < 4; k++) acc[k] += ms[ig*4+k][c]*w;
    }
    #pragma unroll
    for (int k = 0; k < 4; k++)
        g_wibuf[((b*L_ + ig*4+k)*CP_ + p)*C_ + d] = acc[k];
}

// ---------------------------------------------------------------------------
// Kernel B: grid = (b, i-pair), 256 threads. feat in registers, AdaNorm via
// shfl over the 8 pq threads, float4 stores.
// ---------------------------------------------------------------------------
__global__ void __launch_bounds__(256) kB(
    const float* __restrict__ pp_b,
    const float* __restrict__ ada_g, const float* __restrict__ ada_b,
    const float* __restrict__ ada_alpha, float* __restrict__ out)
{
    __shared__ float msB[64*36];
    __shared__ float wiB[2*16*36];
    __shared__ float nrmS[L_];

    const int t = threadIdx.x;
    const int b = blockIdx.x >> 5, i0 = (blockIdx.x & 31) * 2;

    for (int idx = t; idx < L_*C_; idx += 256)
        msB[swz(idx>>5, idx&31)] = g_mbuf[b*L_*C_ + idx];
    for (int idx = t; idx < 2*CP_*C_; idx += 256) {
        const int ii = idx >> 9, p = (idx >> 5) & 15, d = idx & 31;
        wiB[ii*576 + swz(p,d)] = g_wibuf[(b*L_ + i0)*CP_*C_ + idx];
    }
    if (t < L_) nrmS[t] = g_nrm[b*L_ + t];
    __syncthreads();

    const int ii = t >> 7, sub = t & 127;
    const int jg = sub >> 3, j0 = jg*4;
    const int pq = sub & 7;
    const int i = i0 + ii;

    u64 acc[2][4];
    #pragma unroll
    for (int pk = 0; pk < 2; pk++)
        #pragma unroll
        for (int jk = 0; jk < 4; jk++) acc[pk][jk] = 0ull;

    #pragma unroll
    for (int ch = 0; ch < 8; ch++) {
        const int cd = ch*4;
        ulonglong2 mj[4], wp[2];
        #pragma unroll
        for (int jk = 0; jk < 4; jk++)
            mj[jk] = *reinterpret_cast<const ulonglong2*>(&msB[swz(j0+jk, cd)]);
        #pragma unroll
        for (int pk = 0; pk < 2; pk++)
            wp[pk] = *reinterpret_cast<const ulonglong2*>(&wiB[ii*576 + swz(pq+8*pk, cd)]);
        #pragma unroll
        for (int pk = 0; pk < 2; pk++)
            #pragma unroll
            for (int jk = 0; jk < 4; jk++) {
                acc[pk][jk] = fma2(wp[pk].x, mj[jk].x, acc[pk][jk]);
                acc[pk][jk] = fma2(wp[pk].y, mj[jk].y, acc[pk][jk]);
            }
    }

    const float ni = nrmS[i];
    float invd[4];
    #pragma unroll
    for (int jk = 0; jk < 4; jk++)
        invd[jk] = __fdividef(1.f, fmaxf(ni*nrmS[j0+jk], 1e-6f));

    float feat[2][4];
    #pragma unroll
    for (int pk = 0; pk < 2; pk++) {
        const float bp = pp_b[pq + 8*pk];
        #pragma unroll
        for (int jk = 0; jk < 4; jk++) {
            const float2 f = unpack2(acc[pk][jk]);
            feat[pk][jk] = (f.x + f.y)*invd[jk] + bp;
        }
    }

    float s1[4], s2[4];
    #pragma unroll
    for (int jk = 0; jk < 4; jk++) {
        s1[jk] = feat[0][jk] + feat[1][jk];
        s2[jk] = feat[0][jk]*feat[0][jk] + feat[1][jk]*feat[1][jk];
    }
    #pragma unroll
    for (int o = 1; o < 8; o <<= 1) {
        #pragma unroll
        for (int jk = 0; jk < 4; jk++) {
            s1[jk] += __shfl_xor_sync(0xffffffffu, s1[jk], o);
            s2[jk] += __shfl_xor_sync(0xffffffffu, s2[jk], o);
        }
    }
    float mu[4], rsd[4];
    #pragma unroll
    for (int jk = 0; jk < 4; jk++) {
        mu[jk] = s1[jk]*(1.f/CP_);
        rsd[jk] = rsqrtf(s2[jk]*(1.f/CP_) - mu[jk]*mu[jk] + 1e-5f);
    }

    const float alpha = ada_alpha[0];
    #pragma unroll
    for (int pk = 0; pk < 2; pk++) {
        const int p = pq + 8*pk;
        const float g = ada_g[p], bb = ada_b[p];
        float4 r;
        float* rp = &r.x;
        #pragma unroll
        for (int jk = 0; jk < 4; jk++) {
            const float v = feat[pk][jk];
            const float ln = (v - mu[jk])*rsd[jk]*g + bb;
            const float val = v + alpha*ln;
            rp[jk] = __fdividef(val, 1.f + __expf(-val));
        }
        *reinterpret_cast<float4*>(&out[((b*CP_ + p)*L_ + i)*L_ + j0]) = r;
    }
}

extern "C" void kernel_launch(void* const* d_in, const int* in_sizes, int n_in,
                              void* d_out, int out_size) {
    const float* in[29];
    for (int i = 0; i < 29 && i < n_in; i++) in[i] = (const float*)d_in[i];

    cudaFuncSetAttribute(kA, cudaFuncAttributeMaxDynamicSharedMemorySize, KA_SMEM);

    kA<<<B_*S_*2, 512, KA_SMEM>>>(in[0], in[1], in[2], in[3], in[4],
                                  in[5], in[6], in[7], in[8], in[9],
                                  in[10], in[11], in[12], in[13], in[14], in[15],
                                  in[16], in[17], in[18], in[19],
                                  in[20], in[21], in[22], in[23]);
    kW<<<B_*CP_, 512>>>(in[24]);
    kB<<<B_*L_/2, 256>>>(in[25], in[26], in[27], in[28], (float*)d_out);
}

// round 7
// speedup vs baseline: 1.0256x; 1.0256x over previous
#include <cuda_runtime.h>

#define B_ 32
#define S_ 4
#define L_ 64
#define C_ 32
#define H_ 4
#define D_ 8
#define CP_ 16

typedef unsigned long long u64;

__device__ __forceinline__ u64 fma2(u64 a, u64 b, u64 c){
    u64 d; asm("fma.rn.f32x2 %0,%1,%2,%3;" : "=l"(d) : "l"(a),"l"(b),"l"(c)); return d;
}
__device__ __forceinline__ u64 mul2(u64 a, u64 b){
    u64 d; asm("mul.rn.f32x2 %0,%1,%2;" : "=l"(d) : "l"(a),"l"(b)); return d;
}
__device__ __forceinline__ u64 add2(u64 a, u64 b){
    u64 d; asm("add.rn.f32x2 %0,%1,%2;" : "=l"(d) : "l"(a),"l"(b)); return d;
}
__device__ __forceinline__ u64 pack2(float lo, float hi){
    u64 d; asm("mov.b64 %0,{%1,%2};" : "=l"(d) : "f"(lo),"f"(hi)); return d;
}
__device__ __forceinline__ float2 unpack2(u64 v){
    float x,y; asm("mov.b64 {%0,%1},%2;" : "=f"(x),"=f"(y) : "l"(v)); return make_float2(x,y);
}

__device__ float g_xbuf[B_*S_*L_*C_];
__device__ float g_mbuf[B_*L_*C_];      // normalized m-hat
__device__ float g_wibuf[B_*L_*CP_*C_]; // normalized w-hat

__device__ __forceinline__ int keyf(int r){
    return ((((r>>2)&7) ^ (((r>>5)&1)<<2)) << 2);
}
__device__ __forceinline__ int xi(int r, int c){ return r*36 + (c ^ keyf(r)); }
__device__ __forceinline__ int swz(int r, int c){ return r*36 + (c ^ (((r>>2)&7)<<2)); }

// ---------------------------------------------------------------------------
// Kernel A: one block per (b,s), 1024 threads.
// float layout: XS@0 QS@2304 KS@4608 VS@6912 (64x36, xi swizzle)
//   BK@9216 (64x68)  GW@13568(256) GB@13824(32)
// u64 layout (base 6928): WQ2@6928 WK2@7472 WV2@8016 WO2@8560 (32x17 each)
// total 18208 floats = 72832 B
// ---------------------------------------------------------------------------
#define QSOFF 2304
#define KSOFF 4608
#define VSOFF 6912
#define BKOFF 9216
#define GWOFF 13568
#define GBOFF 13824
#define WQ2U 6928
#define WK2U 7472
#define WV2U 8016
#define WO2U 8560
#define KA_SMEM (18208*4)

__global__ void __launch_bounds__(1024) kA(
    const float* __restrict__ chip0, const float* __restrict__ chip1,
    const float* __restrict__ chip2, const float* __restrict__ chip3,
    const float* __restrict__ bulk,
    const float* __restrict__ we_w, const float* __restrict__ we_b,
    const float* __restrict__ pos,
    const float* __restrict__ mn_g, const float* __restrict__ mn_b,
    const float* __restrict__ wq, const float* __restrict__ bq,
    const float* __restrict__ wk, const float* __restrict__ bk,
    const float* __restrict__ wv, const float* __restrict__ bv,
    const float* __restrict__ wo, const float* __restrict__ bo,
    const float* __restrict__ an_g, const float* __restrict__ an_b,
    const float* __restrict__ conv_w, const float* __restrict__ conv_b,
    const float* __restrict__ gate_w, const float* __restrict__ gate_b)
{
    extern __shared__ float sm[];
    u64* smu = reinterpret_cast<u64*>(sm);
    const int t = threadIdx.x;
    const int b = blockIdx.x >> 2, s = blockIdx.x & 3;
    const float* chip = (s==0)?chip0:(s==1)?chip1:(s==2)?chip2:chip3;

    // stage weights as u64 pairs (stride-17 u64 rows -> conflict-free LDS.64)
    for (int idx = t; idx < 512; idx += 1024) {
        const int r = idx >> 4, c2 = idx & 15;
        const int o = r*17 + c2;
        float2 a;
        a = *reinterpret_cast<const float2*>(&wq[idx*2]); smu[WQ2U + o] = *reinterpret_cast<u64*>(&a);
        a = *reinterpret_cast<const float2*>(&wk[idx*2]); smu[WK2U + o] = *reinterpret_cast<u64*>(&a);
        a = *reinterpret_cast<const float2*>(&wv[idx*2]); smu[WV2U + o] = *reinterpret_cast<u64*>(&a);
        a = *reinterpret_cast<const float2*>(&wo[idx*2]); smu[WO2U + o] = *reinterpret_cast<u64*>(&a);
    }
    for (int idx = t; idx < L_*L_; idx += 1024)
        sm[BKOFF + (idx>>6)*68 + (idx&63)] = bulk[b*L_*L_ + idx];
    if (t < 256) sm[GWOFF + t] = gate_w[t];
    if (t >= 256 && t < 288) sm[GBOFF + t - 256] = gate_b[t - 256];

    // phase 1: msa + pos, LN(mn). 16 threads/row, 2 c each.
    {
        const int l = t >> 4, q = t & 15, c0 = q*2;
        const float sig = chip[b*L_ + l];
        const float2 ww = *reinterpret_cast<const float2*>(&we_w[c0]);
        const float2 wb = *reinterpret_cast<const float2*>(&we_b[c0]);
        const float2 pp = *reinterpret_cast<const float2*>(&pos[l*C_ + c0]);
        const float v0 = fmaf(sig, ww.x, wb.x) + pp.x;
        const float v1 = fmaf(sig, ww.y, wb.y) + pp.y;
        float s1 = v0 + v1, s2 = v0*v0 + v1*v1;
        #pragma unroll
        for (int o = 1; o < 16; o <<= 1) {
            s1 += __shfl_xor_sync(0xffffffffu, s1, o);
            s2 += __shfl_xor_sync(0xffffffffu, s2, o);
        }
        const float mean = s1*(1.f/C_);
        const float rstd = rsqrtf(s2*(1.f/C_) - mean*mean + 1e-5f);
        sm[xi(l,c0)]   = (v0-mean)*rstd*mn_g[c0]   + mn_b[c0];
        sm[xi(l,c0+1)] = (v1-mean)*rstd*mn_g[c0+1] + mn_b[c0+1];
    }
    __syncthreads();

    // phase 2: QKV via f32x2. warp -> 2 rows, lane = co (output channel).
    {
        const int co = t & 31, lbase = (t >> 5) * 2;
        const int x0b = lbase*18,     k0h = keyf(lbase)   >> 1;
        const int x1b = (lbase+1)*18, k1h = keyf(lbase+1) >> 1;
        const int wrow = co*17;
        u64 aq0=0, aq1=0, ak0=0, ak1=0, av0=0, av1=0;
        #pragma unroll 8
        for (int c2 = 0; c2 < 16; c2++) {
            const u64 x0 = smu[x0b + (c2 ^ k0h)];
            const u64 x1 = smu[x1b + (c2 ^ k1h)];
            const u64 wqv = smu[WQ2U + wrow + c2];
            const u64 wkv = smu[WK2U + wrow + c2];
            const u64 wvv = smu[WV2U + wrow + c2];
            aq0 = fma2(x0, wqv, aq0); aq1 = fma2(x1, wqv, aq1);
            ak0 = fma2(x0, wkv, ak0); ak1 = fma2(x1, wkv, ak1);
            av0 = fma2(x0, wvv, av0); av1 = fma2(x1, wvv, av1);
        }
        const float ibq = bq[co], ibk = bk[co], ibv = bv[co];
        float2 f;
        f = unpack2(aq0); sm[QSOFF + xi(lbase,co)]   = f.x + f.y + ibq;
        f = unpack2(aq1); sm[QSOFF + xi(lbase+1,co)] = f.x + f.y + ibq;
        f = unpack2(ak0); sm[KSOFF + xi(lbase,co)]   = f.x + f.y + ibk;
        f = unpack2(ak1); sm[KSOFF + xi(lbase+1,co)] = f.x + f.y + ibk;
        f = unpack2(av0); sm[VSOFF + xi(lbase,co)]   = f.x + f.y + ibv;
        f = unpack2(av1); sm[VSOFF + xi(lbase+1,co)] = f.x + f.y + ibv;
    }
    __syncthreads();

    // phase 3: attention. thread = (h, l, quarter); m in [16q, 16q+16).
    {
        const int h = t >> 8, rem = t & 255;
        const int l = rem >> 2, quarter = rem & 3;
        const int hc = h*D_;
        const float rsd = 0.35355339059327373f;

        ulonglong2 qa = *reinterpret_cast<const ulonglong2*>(&sm[QSOFF + xi(l,hc)]);
        ulonglong2 qb = *reinterpret_cast<const ulonglong2*>(&sm[QSOFF + xi(l,hc+4)]);
        const u64 rsd2 = pack2(rsd, rsd);
        qa.x = mul2(qa.x, rsd2); qa.y = mul2(qa.y, rsd2);
        qb.x = mul2(qb.x, rsd2); qb.y = mul2(qb.y, rsd2);
        const float cw = conv_w[h], cb = conv_b[h];

        float Z = 0.f;
        u64 A0 = 0ull, A1 = 0ull, A2 = 0ull, A3 = 0ull;

        #pragma unroll
        for (int g = 0; g < 4; g++) {
            const int m0 = quarter*16 + g*4;
            const float4 bkv = *reinterpret_cast<const float4*>(&sm[BKOFF + l*68 + m0]);
            #pragma unroll
            for (int k = 0; k < 4; k++) {
                const int m = m0 + k;
                const ulonglong2 ka = *reinterpret_cast<const ulonglong2*>(&sm[KSOFF + xi(m,hc)]);
                const ulonglong2 kb = *reinterpret_cast<const ulonglong2*>(&sm[KSOFF + xi(m,hc+4)]);
                u64 u = mul2(qa.x, ka.x);
                u = fma2(qa.y, ka.y, u);
                u = fma2(qb.x, kb.x, u);
                u = fma2(qb.y, kb.y, u);
                const float2 uf = unpack2(u);
                const float sc = uf.x + uf.y + fmaf((&bkv.x)[k], cw, cb);
                const float p = __expf(sc);
                Z += p;
                const u64 pp = pack2(p, p);
                const ulonglong2 va = *reinterpret_cast<const ulonglong2*>(&sm[VSOFF + xi(m,hc)]);
                const ulonglong2 vb = *reinterpret_cast<const ulonglong2*>(&sm[VSOFF + xi(m,hc+4)]);
                A0 = fma2(pp, va.x, A0); A1 = fma2(pp, va.y, A1);
                A2 = fma2(pp, vb.x, A2); A3 = fma2(pp, vb.y, A3);
            }
        }
        #pragma unroll
        for (int o = 1; o < 4; o <<= 1) {
            Z  += __shfl_xor_sync(0xffffffffu, Z, o);
            A0 = add2(A0, __shfl_xor_sync(0xffffffffu, A0, o));
            A1 = add2(A1, __shfl_xor_sync(0xffffffffu, A1, o));
            A2 = add2(A2, __shfl_xor_sync(0xffffffffu, A2, o));
            A3 = add2(A3, __shfl_xor_sync(0xffffffffu, A3, o));
        }

        __syncthreads();
        if (quarter == 0) {
            const float inv = 1.f/Z;
            const float2 f0 = unpack2(A0), f1 = unpack2(A1), f2 = unpack2(A2), f3 = unpack2(A3);
            float o[D_];
            o[0]=f0.x*inv; o[1]=f0.y*inv; o[2]=f1.x*inv; o[3]=f1.y*inv;
            o[4]=f2.x*inv; o[5]=f2.y*inv; o[6]=f3.x*inv; o[7]=f3.y*inv;
            float4 r0, r1;
            #pragma unroll
            for (int d = 0; d < D_; d++) {
                float g = sm[GBOFF + hc + d];
                #pragma unroll
                for (int dd = 0; dd < D_; dd++)
                    g += sm[GWOFF + h*D_*D_ + d*D_ + dd]*o[dd];
                ((d < 4) ? (&r0.x) : (&r1.x))[d & 3] = o[d] / (1.f + __expf(-g));
            }
            *reinterpret_cast<float4*>(&sm[QSOFF + xi(l,hc)])   = r0;
            *reinterpret_cast<float4*>(&sm[QSOFF + xi(l,hc+4)]) = r1;
        }
    }
    __syncthreads();

    // phase 4a: wo + residual -> KS, f32x2. warp -> 2 rows.
    {
        const int co = t & 31, lbase = (t >> 5) * 2;
        const int x0b = lbase*18,     k0h = keyf(lbase)   >> 1;
        const int x1b = (lbase+1)*18, k1h = keyf(lbase+1) >> 1;
        const int wrow = co*17;
        u64 a0 = 0, a1 = 0;
        #pragma unroll 8
        for (int c2 = 0; c2 < 16; c2++) {
            const u64 w = smu[WO2U + wrow + c2];
            a0 = fma2(smu[(QSOFF>>1) + x0b + (c2 ^ k0h)], w, a0);
            a1 = fma2(smu[(QSOFF>>1) + x1b + (c2 ^ k1h)], w, a1);
        }
        const float ib = bo[co];
        float2 f;
        f = unpack2(a0);
        sm[KSOFF + xi(lbase,co)]   = sm[xi(lbase,co)]   + f.x + f.y + ib;
        f = unpack2(a1);
        sm[KSOFF + xi(lbase+1,co)] = sm[xi(lbase+1,co)] + f.x + f.y + ib;
    }
    __syncthreads();

    // phase 4b: LN(an) -> g_xbuf. 16 threads/row, 2 c each.
    {
        const int l = t >> 4, q = t & 15, c0 = q*2;
        const float v0 = sm[KSOFF + xi(l, c0)];
        const float v1 = sm[KSOFF + xi(l, c0+1)];
        float s1 = v0 + v1, s2 = v0*v0 + v1*v1;
        #pragma unroll
        for (int o = 1; o < 16; o <<= 1) {
            s1 += __shfl_xor_sync(0xffffffffu, s1, o);
            s2 += __shfl_xor_sync(0xffffffffu, s2, o);
        }
        const float mean = s1*(1.f/C_);
        const float rstd = rsqrtf(s2*(1.f/C_) - mean*mean + 1e-5f);
        float2 r;
        r.x = (v0-mean)*rstd*an_g[c0]   + an_b[c0];
        r.y = (v1-mean)*rstd*an_g[c0+1] + an_b[c0+1];
        *reinterpret_cast<float2*>(&g_xbuf[((b*S_ + s)*L_ + l)*C_ + c0]) = r;
    }
}

// ---------------------------------------------------------------------------
// Kernel W: max-over-tracks + normalization + wi projection (normalized).
// grid = (b,p) = 512 blocks, 512 threads. p==0 also writes m-hat.
// ---------------------------------------------------------------------------
__global__ void __launch_bounds__(512) kW(const float* __restrict__ pp_w) {
    __shared__ float ms[L_][C_+1];
    __shared__ float pw[C_][C_+1];
    __shared__ float rinv[L_];
    const int t = threadIdx.x;
    const int b = blockIdx.x >> 4, p = blockIdx.x & 15;
    const float* xb = g_xbuf + b*S_*L_*C_;

    for (int idx = t; idx < L_*C_; idx += 512) {
        const float m = fmaxf(fmaxf(xb[idx], xb[2048+idx]),
                              fmaxf(xb[4096+idx], xb[6144+idx]));
        ms[idx>>5][idx&31] = m;
    }
    for (int idx = t; idx < C_*C_; idx += 512)
        pw[idx>>5][idx&31] = pp_w[p*C_*C_ + idx];
    __syncthreads();

    if (t < L_) {
        float ssum = 0.f;
        #pragma unroll
        for (int c = 0; c < C_; c++) { const float v = ms[t][c]; ssum += v*v; }
        rinv[t] = rsqrtf(ssum);
    }
    __syncthreads();

    if (p == 0) {
        for (int idx = t; idx < L_*C_; idx += 512)
            g_mbuf[b*L_*C_ + idx] = ms[idx>>5][idx&31] * rinv[idx>>5];
    }

    const int d = t & 31, ig = t >> 5;     // 16 groups x 4 i's
    float acc[4];
    #pragma unroll
    for (int k = 0; k < 4; k++) acc[k] = 0.f;
    #pragma unroll 8
    for (int c = 0; c < C_; c++) {
        const float w = pw[c][d];
        #pragma unroll
        for (int k = 0; k < 4; k++) acc[k] += ms[ig*4+k][c]*w;
    }
    #pragma unroll
    for (int k = 0; k < 4; k++)
        g_wibuf[((b*L_ + ig*4+k)*CP_ + p)*C_ + d] = acc[k] * rinv[ig*4+k];
}

// ---------------------------------------------------------------------------
// Kernel B: grid = (b, i-pair), 256 threads. Pre-normalized inputs; feat in
// registers, AdaNorm via shfl over the 8 pq threads, float4 stores.
// ---------------------------------------------------------------------------
__global__ void __launch_bounds__(256) kB(
    const float* __restrict__ pp_b,
    const float* __restrict__ ada_g, const float* __restrict__ ada_b,
    const float* __restrict__ ada_alpha, float* __restrict__ out)
{
    __shared__ float msB[64*36];
    __shared__ float wiB[2*16*36];

    const int t = threadIdx.x;
    const int b = blockIdx.x >> 5, i0 = (blockIdx.x & 31) * 2;

    for (int idx = t; idx < L_*C_; idx += 256)
        msB[swz(idx>>5, idx&31)] = g_mbuf[b*L_*C_ + idx];
    for (int idx = t; idx < 2*CP_*C_; idx += 256) {
        const int ii = idx >> 9, p = (idx >> 5) & 15, d = idx & 31;
        wiB[ii*576 + swz(p,d)] = g_wibuf[(b*L_ + i0)*CP_*C_ + idx];
    }
    __syncthreads();

    const int ii = t >> 7, sub = t & 127;
    const int jg = sub >> 3, j0 = jg*4;
    const int pq = sub & 7;
    const int i = i0 + ii;

    u64 acc[2][4];
    #pragma unroll
    for (int pk = 0; pk < 2; pk++)
        #pragma unroll
        for (int jk = 0; jk < 4; jk++) acc[pk][jk] = 0ull;

    #pragma unroll
    for (int ch = 0; ch < 8; ch++) {
        const int cd = ch*4;
        ulonglong2 mj[4], wp[2];
        #pragma unroll
        for (int jk = 0; jk < 4; jk++)
            mj[jk] = *reinterpret_cast<const ulonglong2*>(&msB[swz(j0+jk, cd)]);
        #pragma unroll
        for (int pk = 0; pk < 2; pk++)
            wp[pk] = *reinterpret_cast<const ulonglong2*>(&wiB[ii*576 + swz(pq+8*pk, cd)]);
        #pragma unroll
        for (int pk = 0; pk < 2; pk++)
            #pragma unroll
            for (int jk = 0; jk < 4; jk++) {
                acc[pk][jk] = fma2(wp[pk].x, mj[jk].x, acc[pk][jk]);
                acc[pk][jk] = fma2(wp[pk].y, mj[jk].y, acc[pk][jk]);
            }
    }

    float feat[2][4];
    #pragma unroll
    for (int pk = 0; pk < 2; pk++) {
        const float bp = pp_b[pq + 8*pk];
        #pragma unroll
        for (int jk = 0; jk < 4; jk++) {
            const float2 f = unpack2(acc[pk][jk]);
            feat[pk][jk] = f.x + f.y + bp;
        }
    }

    float s1[4], s2[4];
    #pragma unroll
    for (int jk = 0; jk < 4; jk++) {
        s1[jk] = feat[0][jk] + feat[1][jk];
        s2[jk] = feat[0][jk]*feat[0][jk] + feat[1][jk]*feat[1][jk];
    }
    #pragma unroll
    for (int o = 1; o < 8; o <<= 1) {
        #pragma unroll
        for (int jk = 0; jk < 4; jk++) {
            s1[jk] += __shfl_xor_sync(0xffffffffu, s1[jk], o);
            s2[jk] += __shfl_xor_sync(0xffffffffu, s2[jk], o);
        }
    }
    float mu[4], rsd[4];
    #pragma unroll
    for (int jk = 0; jk < 4; jk++) {
        mu[jk] = s1[jk]*(1.f/CP_);
        rsd[jk] = rsqrtf(s2[jk]*(1.f/CP_) - mu[jk]*mu[jk] + 1e-5f);
    }

    const float alpha = ada_alpha[0];
    #pragma unroll
    for (int pk = 0; pk < 2; pk++) {
        const int p = pq + 8*pk;
        const float g = ada_g[p], bb = ada_b[p];
        float4 r;
        float* rp = &r.x;
        #pragma unroll
        for (int jk = 0; jk < 4; jk++) {
            const float v = feat[pk][jk];
            const float ln = (v - mu[jk])*rsd[jk]*g + bb;
            const float val = v + alpha*ln;
            rp[jk] = __fdividef(val, 1.f + __expf(-val));
        }
        *reinterpret_cast<float4*>(&out[((b*CP_ + p)*L_ + i)*L_ + j0]) = r;
    }
}

extern "C" void kernel_launch(void* const* d_in, const int* in_sizes, int n_in,
                              void* d_out, int out_size) {
    const float* in[29];
    for (int i = 0; i < 29 && i < n_in; i++) in[i] = (const float*)d_in[i];

    cudaFuncSetAttribute(kA, cudaFuncAttributeMaxDynamicSharedMemorySize, KA_SMEM);

    kA<<<B_*S_, 1024, KA_SMEM>>>(in[0], in[1], in[2], in[3], in[4],
                                 in[5], in[6], in[7], in[8], in[9],
                                 in[10], in[11], in[12], in[13], in[14], in[15],
                                 in[16], in[17], in[18], in[19],
                                 in[20], in[21], in[22], in[23]);
    kW<<<B_*CP_, 512>>>(in[24]);
    kB<<<B_*L_/2, 256>>>(in[25], in[26], in[27], in[28], (float*)d_out);
}

// round 8
// speedup vs baseline: 1.1652x; 1.1361x over previous
#include <cuda_runtime.h>

#define B_ 32
#define S_ 4
#define L_ 64
#define C_ 32
#define H_ 4
#define D_ 8
#define CP_ 16

typedef unsigned long long u64;

__device__ __forceinline__ u64 fma2(u64 a, u64 b, u64 c){
    u64 d; asm("fma.rn.f32x2 %0,%1,%2,%3;" : "=l"(d) : "l"(a),"l"(b),"l"(c)); return d;
}
__device__ __forceinline__ u64 mul2(u64 a, u64 b){
    u64 d; asm("mul.rn.f32x2 %0,%1,%2;" : "=l"(d) : "l"(a),"l"(b)); return d;
}
__device__ __forceinline__ u64 add2(u64 a, u64 b){
    u64 d; asm("add.rn.f32x2 %0,%1,%2;" : "=l"(d) : "l"(a),"l"(b)); return d;
}
__device__ __forceinline__ u64 pack2(float lo, float hi){
    u64 d; asm("mov.b64 %0,{%1,%2};" : "=l"(d) : "f"(lo),"f"(hi)); return d;
}
__device__ __forceinline__ float2 unpack2(u64 v){
    float x,y; asm("mov.b64 {%0,%1},%2;" : "=f"(x),"=f"(y) : "l"(v)); return make_float2(x,y);
}

__device__ float g_xbuf[B_*S_*L_*C_];
__device__ float g_mbuf[B_*L_*C_];      // normalized m-hat
__device__ float g_wibuf[B_*L_*CP_*C_]; // normalized w-hat

__device__ __forceinline__ int keyf(int r){
    return ((((r>>2)&7) ^ (((r>>5)&1)<<2)) << 2);
}
__device__ __forceinline__ int xi(int r, int c){ return r*36 + (c ^ keyf(r)); }
__device__ __forceinline__ int swz(int r, int c){ return r*36 + (c ^ (((r>>2)&7)<<2)); }

// ---------------------------------------------------------------------------
// Kernel A: one block per (b,s), 1024 threads.
// float layout: XS@0 QS@2304 KS@4608 VS@6912 (64x36, xi swizzle)
//   BK@9216 (two 4225-float planes, R5 layout)  GW@17666(256) GB@17922(32)
// u64 layout: WQ2@9056 WK2@9600 WV2@10144 WO2@10688 (32x17 u64 each)
//   (u64 region floats 18112..22464)
// total 22466 floats = 89864 B
// ---------------------------------------------------------------------------
#define QSOFF 2304
#define KSOFF 4608
#define VSOFF 6912
#define GWOFF 17666
#define GBOFF 17922
#define WQ2U 9056
#define WK2U 9600
#define WV2U 10144
#define WO2U 10688
#define KA_SMEM (22466*4)
#define BKI(l,m) (9216 + ((m)>>5)*4225 + (l)*66 + ((m)&31))

__global__ void __launch_bounds__(1024) kA(
    const float* __restrict__ chip0, const float* __restrict__ chip1,
    const float* __restrict__ chip2, const float* __restrict__ chip3,
    const float* __restrict__ bulk,
    const float* __restrict__ we_w, const float* __restrict__ we_b,
    const float* __restrict__ pos,
    const float* __restrict__ mn_g, const float* __restrict__ mn_b,
    const float* __restrict__ wq, const float* __restrict__ bq,
    const float* __restrict__ wk, const float* __restrict__ bk,
    const float* __restrict__ wv, const float* __restrict__ bv,
    const float* __restrict__ wo, const float* __restrict__ bo,
    const float* __restrict__ an_g, const float* __restrict__ an_b,
    const float* __restrict__ conv_w, const float* __restrict__ conv_b,
    const float* __restrict__ gate_w, const float* __restrict__ gate_b)
{
    extern __shared__ float sm[];
    u64* smu = reinterpret_cast<u64*>(sm);
    const int t = threadIdx.x;
    const int b = blockIdx.x >> 2, s = blockIdx.x & 3;
    const float* chip = (s==0)?chip0:(s==1)?chip1:(s==2)?chip2:chip3;

    // stage weights as u64 pairs: row stride 17 u64 (conflict-free LDS.64)
    for (int idx = t; idx < 512; idx += 1024) {
        const int r = idx >> 4, c2 = idx & 15;
        const int o = r*17 + c2;
        float2 a;
        a = *reinterpret_cast<const float2*>(&wq[idx*2]); smu[WQ2U + o] = *reinterpret_cast<u64*>(&a);
        a = *reinterpret_cast<const float2*>(&wk[idx*2]); smu[WK2U + o] = *reinterpret_cast<u64*>(&a);
        a = *reinterpret_cast<const float2*>(&wv[idx*2]); smu[WV2U + o] = *reinterpret_cast<u64*>(&a);
        a = *reinterpret_cast<const float2*>(&wo[idx*2]); smu[WO2U + o] = *reinterpret_cast<u64*>(&a);
    }
    for (int idx = t; idx < L_*L_; idx += 1024)
        sm[BKI(idx>>6, idx&63)] = bulk[b*L_*L_ + idx];
    if (t < 256) sm[GWOFF + t] = gate_w[t];
    if (t >= 256 && t < 288) sm[GBOFF + t - 256] = gate_b[t - 256];

    // phase 1: msa + pos, LN(mn). 16 threads/row, 2 c each. (R5)
    {
        const int l = t >> 4, q = t & 15, c0 = q*2;
        const float sig = chip[b*L_ + l];
        const float2 ww = *reinterpret_cast<const float2*>(&we_w[c0]);
        const float2 wb = *reinterpret_cast<const float2*>(&we_b[c0]);
        const float2 pp = *reinterpret_cast<const float2*>(&pos[l*C_ + c0]);
        const float v0 = fmaf(sig, ww.x, wb.x) + pp.x;
        const float v1 = fmaf(sig, ww.y, wb.y) + pp.y;
        float s1 = v0 + v1, s2 = v0*v0 + v1*v1;
        #pragma unroll
        for (int o = 1; o < 16; o <<= 1) {
            s1 += __shfl_xor_sync(0xffffffffu, s1, o);
            s2 += __shfl_xor_sync(0xffffffffu, s2, o);
        }
        const float mean = s1*(1.f/C_);
        const float rstd = rsqrtf(s2*(1.f/C_) - mean*mean + 1e-5f);
        sm[xi(l,c0)]   = (v0-mean)*rstd*mn_g[c0]   + mn_b[c0];
        sm[xi(l,c0+1)] = (v1-mean)*rstd*mn_g[c0+1] + mn_b[c0+1];
    }
    __syncthreads();

    // phase 2: QKV via f32x2/u64. warp -> 2 rows, lane = co.
    {
        const int co = t & 31, lbase = (t >> 5) * 2;
        const int x0b = lbase*18,     k0h = keyf(lbase)   >> 1;
        const int x1b = (lbase+1)*18, k1h = keyf(lbase+1) >> 1;
        const int wrow = co*17;
        u64 aq0=0, aq1=0, ak0=0, ak1=0, av0=0, av1=0;
        #pragma unroll 8
        for (int c2 = 0; c2 < 16; c2++) {
            const u64 x0 = smu[x0b + (c2 ^ k0h)];       // broadcast
            const u64 x1 = smu[x1b + (c2 ^ k1h)];       // broadcast
            const u64 wqv = smu[WQ2U + wrow + c2];
            const u64 wkv = smu[WK2U + wrow + c2];
            const u64 wvv = smu[WV2U + wrow + c2];
            aq0 = fma2(x0, wqv, aq0); aq1 = fma2(x1, wqv, aq1);
            ak0 = fma2(x0, wkv, ak0); ak1 = fma2(x1, wkv, ak1);
            av0 = fma2(x0, wvv, av0); av1 = fma2(x1, wvv, av1);
        }
        const float ibq = bq[co], ibk = bk[co], ibv = bv[co];
        float2 f;
        f = unpack2(aq0); sm[QSOFF + xi(lbase,co)]   = f.x + f.y + ibq;
        f = unpack2(aq1); sm[QSOFF + xi(lbase+1,co)] = f.x + f.y + ibq;
        f = unpack2(ak0); sm[KSOFF + xi(lbase,co)]   = f.x + f.y + ibk;
        f = unpack2(ak1); sm[KSOFF + xi(lbase+1,co)] = f.x + f.y + ibk;
        f = unpack2(av0); sm[VSOFF + xi(lbase,co)]   = f.x + f.y + ibv;
        f = unpack2(av1); sm[VSOFF + xi(lbase+1,co)] = f.x + f.y + ibv;
    }
    __syncthreads();

    // phase 3: attention (R5 exact: interleaved m = 4*mm + quarter).
    {
        const int h = t >> 8, rem = t & 255;
        const int l = rem >> 2, quarter = rem & 3;
        const int hc = h*D_;
        const float rsd = 0.35355339059327373f;

        ulonglong2 qa = *reinterpret_cast<const ulonglong2*>(&sm[QSOFF + xi(l,hc)]);
        ulonglong2 qb = *reinterpret_cast<const ulonglong2*>(&sm[QSOFF + xi(l,hc+4)]);
        const u64 rsd2 = pack2(rsd, rsd);
        qa.x = mul2(qa.x, rsd2); qa.y = mul2(qa.y, rsd2);
        qb.x = mul2(qb.x, rsd2); qb.y = mul2(qb.y, rsd2);
        const float cw = conv_w[h], cb = conv_b[h];

        float Z = 0.f;
        u64 A0 = 0ull, A1 = 0ull, A2 = 0ull, A3 = 0ull;

        #pragma unroll 4
        for (int mm = 0; mm < 16; mm++) {
            const int m = mm*4 + quarter;
            const ulonglong2 ka = *reinterpret_cast<const ulonglong2*>(&sm[KSOFF + xi(m,hc)]);
            const ulonglong2 kb = *reinterpret_cast<const ulonglong2*>(&sm[KSOFF + xi(m,hc+4)]);
            u64 u = mul2(qa.x, ka.x);
            u = fma2(qa.y, ka.y, u);
            u = fma2(qb.x, kb.x, u);
            u = fma2(qb.y, kb.y, u);
            const float2 uf = unpack2(u);
            const float sc = uf.x + uf.y + fmaf(sm[BKI(l,m)], cw, cb);
            const float p = __expf(sc);
            Z += p;
            const u64 pp = pack2(p, p);
            const ulonglong2 va = *reinterpret_cast<const ulonglong2*>(&sm[VSOFF + xi(m,hc)]);
            const ulonglong2 vb = *reinterpret_cast<const ulonglong2*>(&sm[VSOFF + xi(m,hc+4)]);
            A0 = fma2(pp, va.x, A0); A1 = fma2(pp, va.y, A1);
            A2 = fma2(pp, vb.x, A2); A3 = fma2(pp, vb.y, A3);
        }
        #pragma unroll
        for (int o = 1; o < 4; o <<= 1) {
            Z  += __shfl_xor_sync(0xffffffffu, Z, o);
            A0 = add2(A0, __shfl_xor_sync(0xffffffffu, A0, o));
            A1 = add2(A1, __shfl_xor_sync(0xffffffffu, A1, o));
            A2 = add2(A2, __shfl_xor_sync(0xffffffffu, A2, o));
            A3 = add2(A3, __shfl_xor_sync(0xffffffffu, A3, o));
        }

        __syncthreads();
        if (quarter == 0) {
            const float inv = 1.f/Z;
            const float2 f0 = unpack2(A0), f1 = unpack2(A1), f2 = unpack2(A2), f3 = unpack2(A3);
            float o[D_];
            o[0]=f0.x*inv; o[1]=f0.y*inv; o[2]=f1.x*inv; o[3]=f1.y*inv;
            o[4]=f2.x*inv; o[5]=f2.y*inv; o[6]=f3.x*inv; o[7]=f3.y*inv;
            float4 r0, r1;
            #pragma unroll
            for (int d = 0; d < D_; d++) {
                float g = sm[GBOFF + hc + d];
                #pragma unroll
                for (int dd = 0; dd < D_; dd++)
                    g += sm[GWOFF + h*D_*D_ + d*D_ + dd]*o[dd];
                ((d < 4) ? (&r0.x) : (&r1.x))[d & 3] = o[d] / (1.f + __expf(-g));
            }
            *reinterpret_cast<float4*>(&sm[QSOFF + xi(l,hc)])   = r0;
            *reinterpret_cast<float4*>(&sm[QSOFF + xi(l,hc+4)]) = r1;
        }
    }
    __syncthreads();

    // phase 4a: wo + residual -> KS, f32x2/u64. warp -> 2 rows.
    {
        const int co = t & 31, lbase = (t >> 5) * 2;
        const int x0b = lbase*18,     k0h = keyf(lbase)   >> 1;
        const int x1b = (lbase+1)*18, k1h = keyf(lbase+1) >> 1;
        const int wrow = co*17;
        u64 a0 = 0, a1 = 0;
        #pragma unroll 8
        for (int c2 = 0; c2 < 16; c2++) {
            const u64 w = smu[WO2U + wrow + c2];
            a0 = fma2(smu[(QSOFF>>1) + x0b + (c2 ^ k0h)], w, a0);
            a1 = fma2(smu[(QSOFF>>1) + x1b + (c2 ^ k1h)], w, a1);
        }
        const float ib = bo[co];
        float2 f;
        f = unpack2(a0);
        sm[KSOFF + xi(lbase,co)]   = sm[xi(lbase,co)]   + f.x + f.y + ib;
        f = unpack2(a1);
        sm[KSOFF + xi(lbase+1,co)] = sm[xi(lbase+1,co)] + f.x + f.y + ib;
    }
    __syncthreads();

    // phase 4b: LN(an) -> g_xbuf. 16 threads/row, 2 c each. (R5)
    {
        const int l = t >> 4, q = t & 15, c0 = q*2;
        const float v0 = sm[KSOFF + xi(l, c0)];
        const float v1 = sm[KSOFF + xi(l, c0+1)];
        float s1 = v0 + v1, s2 = v0*v0 + v1*v1;
        #pragma unroll
        for (int o = 1; o < 16; o <<= 1) {
            s1 += __shfl_xor_sync(0xffffffffu, s1, o);
            s2 += __shfl_xor_sync(0xffffffffu, s2, o);
        }
        const float mean = s1*(1.f/C_);
        const float rstd = rsqrtf(s2*(1.f/C_) - mean*mean + 1e-5f);
        float2 r;
        r.x = (v0-mean)*rstd*an_g[c0]   + an_b[c0];
        r.y = (v1-mean)*rstd*an_g[c0+1] + an_b[c0+1];
        *reinterpret_cast<float2*>(&g_xbuf[((b*S_ + s)*L_ + l)*C_ + c0]) = r;
    }
}

// ---------------------------------------------------------------------------
// Kernel W: max-over-tracks + normalization + wi projection (normalized).
// grid = (b,p) = 512 blocks, 512 threads. p==0 also writes m-hat.
// ---------------------------------------------------------------------------
__global__ void __launch_bounds__(512) kW(const float* __restrict__ pp_w) {
    __shared__ float ms[L_][C_+1];
    __shared__ float pw[C_][C_+1];
    __shared__ float rinv[L_];
    const int t = threadIdx.x;
    const int b = blockIdx.x >> 4, p = blockIdx.x & 15;
    const float* xb = g_xbuf + b*S_*L_*C_;

    for (int idx = t; idx < L_*C_; idx += 512) {
        const float m = fmaxf(fmaxf(xb[idx], xb[2048+idx]),
                              fmaxf(xb[4096+idx], xb[6144+idx]));
        ms[idx>>5][idx&31] = m;
    }
    for (int idx = t; idx < C_*C_; idx += 512)
        pw[idx>>5][idx&31] = pp_w[p*C_*C_ + idx];
    __syncthreads();

    if (t < L_) {
        float ssum = 0.f;
        #pragma unroll
        for (int c = 0; c < C_; c++) { const float v = ms[t][c]; ssum += v*v; }
        rinv[t] = rsqrtf(ssum);
    }
    __syncthreads();

    if (p == 0) {
        for (int idx = t; idx < L_*C_; idx += 512)
            g_mbuf[b*L_*C_ + idx] = ms[idx>>5][idx&31] * rinv[idx>>5];
    }

    const int d = t & 31, ig = t >> 5;
    float acc[4];
    #pragma unroll
    for (int k = 0; k < 4; k++) acc[k] = 0.f;
    #pragma unroll 8
    for (int c = 0; c < C_; c++) {
        const float w = pw[c][d];
        #pragma unroll
        for (int k = 0; k < 4; k++) acc[k] += ms[ig*4+k][c]*w;
    }
    #pragma unroll
    for (int k = 0; k < 4; k++)
        g_wibuf[((b*L_ + ig*4+k)*CP_ + p)*C_ + d] = acc[k] * rinv[ig*4+k];
}

// ---------------------------------------------------------------------------
// Kernel B: grid = (b, i-quad) = 256 blocks, 512 threads. 4 i's per block.
// Pre-normalized inputs; feat in registers; AdaNorm via shfl; float4 stores.
// ---------------------------------------------------------------------------
__global__ void __launch_bounds__(512) kB(
    const float* __restrict__ pp_b,
    const float* __restrict__ ada_g, const float* __restrict__ ada_b,
    const float* __restrict__ ada_alpha, float* __restrict__ out)
{
    __shared__ float msB[64*36];
    __shared__ float wiB[4*16*36];

    const int t = threadIdx.x;
    const int b = blockIdx.x >> 4, i0 = (blockIdx.x & 15) * 4;

    for (int idx = t; idx < L_*C_; idx += 512)
        msB[swz(idx>>5, idx&31)] = g_mbuf[b*L_*C_ + idx];
    for (int idx = t; idx < 4*CP_*C_; idx += 512) {
        const int ii = idx >> 9, p = (idx >> 5) & 15, d = idx & 31;
        wiB[ii*576 + swz(p,d)] = g_wibuf[(b*L_ + i0)*CP_*C_ + idx];
    }
    __syncthreads();

    const int ii = t >> 7, sub = t & 127;
    const int jg = sub >> 3, j0 = jg*4;
    const int pq = sub & 7;
    const int i = i0 + ii;

    u64 acc[2][4];
    #pragma unroll
    for (int pk = 0; pk < 2; pk++)
        #pragma unroll
        for (int jk = 0; jk < 4; jk++) acc[pk][jk] = 0ull;

    #pragma unroll
    for (int ch = 0; ch < 8; ch++) {
        const int cd = ch*4;
        ulonglong2 mj[4], wp[2];
        #pragma unroll
        for (int jk = 0; jk < 4; jk++)
            mj[jk] = *reinterpret_cast<const ulonglong2*>(&msB[swz(j0+jk, cd)]);
        #pragma unroll
        for (int pk = 0; pk < 2; pk++)
            wp[pk] = *reinterpret_cast<const ulonglong2*>(&wiB[ii*576 + swz(pq+8*pk, cd)]);
        #pragma unroll
        for (int pk = 0; pk < 2; pk++)
            #pragma unroll
            for (int jk = 0; jk < 4; jk++) {
                acc[pk][jk] = fma2(wp[pk].x, mj[jk].x, acc[pk][jk]);
                acc[pk][jk] = fma2(wp[pk].y, mj[jk].y, acc[pk][jk]);
            }
    }

    float feat[2][4];
    #pragma unroll
    for (int pk = 0; pk < 2; pk++) {
        const float bp = pp_b[pq + 8*pk];
        #pragma unroll
        for (int jk = 0; jk < 4; jk++) {
            const float2 f = unpack2(acc[pk][jk]);
            feat[pk][jk] = f.x + f.y + bp;
        }
    }

    float s1[4], s2[4];
    #pragma unroll
    for (int jk = 0; jk < 4; jk++) {
        s1[jk] = feat[0][jk] + feat[1][jk];
        s2[jk] = feat[0][jk]*feat[0][jk] + feat[1][jk]*feat[1][jk];
    }
    #pragma unroll
    for (int o = 1; o < 8; o <<= 1) {
        #pragma unroll
        for (int jk = 0; jk < 4; jk++) {
            s1[jk] += __shfl_xor_sync(0xffffffffu, s1[jk], o);
            s2[jk] += __shfl_xor_sync(0xffffffffu, s2[jk], o);
        }
    }
    float mu[4], rsd[4];
    #pragma unroll
    for (int jk = 0; jk < 4; jk++) {
        mu[jk] = s1[jk]*(1.f/CP_);
        rsd[jk] = rsqrtf(s2[jk]*(1.f/CP_) - mu[jk]*mu[jk] + 1e-5f);
    }

    const float alpha = ada_alpha[0];
    #pragma unroll
    for (int pk = 0; pk < 2; pk++) {
        const int p = pq + 8*pk;
        const float g = ada_g[p], bb = ada_b[p];
        float4 r;
        float* rp = &r.x;
        #pragma unroll
        for (int jk = 0; jk < 4; jk++) {
            const float v = feat[pk][jk];
            const float ln = (v - mu[jk])*rsd[jk]*g + bb;
            const float val = v + alpha*ln;
            rp[jk] = __fdividef(val, 1.f + __expf(-val));
        }
        *reinterpret_cast<float4*>(&out[((b*CP_ + p)*L_ + i)*L_ + j0]) = r;
    }
}

extern "C" void kernel_launch(void* const* d_in, const int* in_sizes, int n_in,
                              void* d_out, int out_size) {
    const float* in[29];
    for (int i = 0; i < 29 && i < n_in; i++) in[i] = (const float*)d_in[i];

    cudaFuncSetAttribute(kA, cudaFuncAttributeMaxDynamicSharedMemorySize, KA_SMEM);

    kA<<<B_*S_, 1024, KA_SMEM>>>(in[0], in[1], in[2], in[3], in[4],
                                 in[5], in[6], in[7], in[8], in[9],
                                 in[10], in[11], in[12], in[13], in[14], in[15],
                                 in[16], in[17], in[18], in[19],
                                 in[20], in[21], in[22], in[23]);
    kW<<<B_*CP_, 512>>>(in[24]);
    kB<<<B_*L_/4, 512>>>(in[25], in[26], in[27], in[28], (float*)d_out);
}

// round 9
// speedup vs baseline: 1.3087x; 1.1231x over previous
#include <cuda_runtime.h>

#define B_ 32
#define S_ 4
#define L_ 64
#define C_ 32
#define H_ 4
#define D_ 8
#define CP_ 16

typedef unsigned long long u64;

__device__ __forceinline__ u64 fma2(u64 a, u64 b, u64 c){
    u64 d; asm("fma.rn.f32x2 %0,%1,%2,%3;" : "=l"(d) : "l"(a),"l"(b),"l"(c)); return d;
}
__device__ __forceinline__ u64 mul2(u64 a, u64 b){
    u64 d; asm("mul.rn.f32x2 %0,%1,%2;" : "=l"(d) : "l"(a),"l"(b)); return d;
}
__device__ __forceinline__ u64 add2(u64 a, u64 b){
    u64 d; asm("add.rn.f32x2 %0,%1,%2;" : "=l"(d) : "l"(a),"l"(b)); return d;
}
__device__ __forceinline__ u64 pack2(float lo, float hi){
    u64 d; asm("mov.b64 %0,{%1,%2};" : "=l"(d) : "f"(lo),"f"(hi)); return d;
}
__device__ __forceinline__ float2 unpack2(u64 v){
    float x,y; asm("mov.b64 {%0,%1},%2;" : "=f"(x),"=f"(y) : "l"(v)); return make_float2(x,y);
}

__device__ float g_xbuf[B_*S_*L_*C_];

__device__ __forceinline__ int keyf(int r){
    return ((((r>>2)&7) ^ (((r>>5)&1)<<2)) << 2);
}
__device__ __forceinline__ int xi(int r, int c){ return r*36 + (c ^ keyf(r)); }
__device__ __forceinline__ int swz(int r, int c){ return r*36 + (c ^ (((r>>2)&7)<<2)); }
__device__ __forceinline__ int swzp(int p, int c){ return p*40 + (c ^ (((p>>2)&7)<<2)); }

// ---------------------------------------------------------------------------
// Kernel A: one block per (b,s), 1024 threads. (R8 structure, new epilogues)
// floats: XS@0 QS@2304 KS@4608 VS@6912 (64x36 xi swizzle)
//   BK@9216 (two 4225-float planes)  GW@17668(256) GB@17924(32)
// u64: WQ2@9056 WK2@9600 WV2@10144 WO2@10688 (32x17 u64 each; floats 18112+)
// ---------------------------------------------------------------------------
#define QSOFF 2304
#define KSOFF 4608
#define VSOFF 6912
#define GWOFF 17668
#define GBOFF 17924
#define WQ2U 9056
#define WK2U 9600
#define WV2U 10144
#define WO2U 10688
#define KA_SMEM (22466*4)
#define BKI(l,m) (9216 + ((m)>>5)*4225 + (l)*66 + ((m)&31))

__global__ void __launch_bounds__(1024) kA(
    const float* __restrict__ chip0, const float* __restrict__ chip1,
    const float* __restrict__ chip2, const float* __restrict__ chip3,
    const float* __restrict__ bulk,
    const float* __restrict__ we_w, const float* __restrict__ we_b,
    const float* __restrict__ pos,
    const float* __restrict__ mn_g, const float* __restrict__ mn_b,
    const float* __restrict__ wq, const float* __restrict__ bq,
    const float* __restrict__ wk, const float* __restrict__ bk,
    const float* __restrict__ wv, const float* __restrict__ bv,
    const float* __restrict__ wo, const float* __restrict__ bo,
    const float* __restrict__ an_g, const float* __restrict__ an_b,
    const float* __restrict__ conv_w, const float* __restrict__ conv_b,
    const float* __restrict__ gate_w, const float* __restrict__ gate_b)
{
    extern __shared__ float sm[];
    u64* smu = reinterpret_cast<u64*>(sm);
    const int t = threadIdx.x;
    const int b = blockIdx.x >> 2, s = blockIdx.x & 3;
    const float* chip = (s==0)?chip0:(s==1)?chip1:(s==2)?chip2:chip3;

    for (int idx = t; idx < 512; idx += 1024) {
        const int r = idx >> 4, c2 = idx & 15;
        const int o = r*17 + c2;
        float2 a;
        a = *reinterpret_cast<const float2*>(&wq[idx*2]); smu[WQ2U + o] = *reinterpret_cast<u64*>(&a);
        a = *reinterpret_cast<const float2*>(&wk[idx*2]); smu[WK2U + o] = *reinterpret_cast<u64*>(&a);
        a = *reinterpret_cast<const float2*>(&wv[idx*2]); smu[WV2U + o] = *reinterpret_cast<u64*>(&a);
        a = *reinterpret_cast<const float2*>(&wo[idx*2]); smu[WO2U + o] = *reinterpret_cast<u64*>(&a);
    }
    for (int idx = t; idx < L_*L_; idx += 1024)
        sm[BKI(idx>>6, idx&63)] = bulk[b*L_*L_ + idx];
    if (t < 256) sm[GWOFF + t] = gate_w[t];
    if (t >= 256 && t < 288) sm[GBOFF + t - 256] = gate_b[t - 256];

    // phase 1: msa + pos, LN(mn). 16 threads/row.
    {
        const int l = t >> 4, q = t & 15, c0 = q*2;
        const float sig = chip[b*L_ + l];
        const float2 ww = *reinterpret_cast<const float2*>(&we_w[c0]);
        const float2 wb = *reinterpret_cast<const float2*>(&we_b[c0]);
        const float2 pp = *reinterpret_cast<const float2*>(&pos[l*C_ + c0]);
        const float v0 = fmaf(sig, ww.x, wb.x) + pp.x;
        const float v1 = fmaf(sig, ww.y, wb.y) + pp.y;
        float s1 = v0 + v1, s2 = v0*v0 + v1*v1;
        #pragma unroll
        for (int o = 1; o < 16; o <<= 1) {
            s1 += __shfl_xor_sync(0xffffffffu, s1, o);
            s2 += __shfl_xor_sync(0xffffffffu, s2, o);
        }
        const float mean = s1*(1.f/C_);
        const float rstd = rsqrtf(s2*(1.f/C_) - mean*mean + 1e-5f);
        sm[xi(l,c0)]   = (v0-mean)*rstd*mn_g[c0]   + mn_b[c0];
        sm[xi(l,c0+1)] = (v1-mean)*rstd*mn_g[c0+1] + mn_b[c0+1];
    }
    __syncthreads();

    // phase 2: QKV via f32x2/u64. warp -> 2 rows, lane = co.
    {
        const int co = t & 31, lbase = (t >> 5) * 2;
        const int x0b = lbase*18,     k0h = keyf(lbase)   >> 1;
        const int x1b = (lbase+1)*18, k1h = keyf(lbase+1) >> 1;
        const int wrow = co*17;
        u64 aq0=0, aq1=0, ak0=0, ak1=0, av0=0, av1=0;
        #pragma unroll 8
        for (int c2 = 0; c2 < 16; c2++) {
            const u64 x0 = smu[x0b + (c2 ^ k0h)];
            const u64 x1 = smu[x1b + (c2 ^ k1h)];
            const u64 wqv = smu[WQ2U + wrow + c2];
            const u64 wkv = smu[WK2U + wrow + c2];
            const u64 wvv = smu[WV2U + wrow + c2];
            aq0 = fma2(x0, wqv, aq0); aq1 = fma2(x1, wqv, aq1);
            ak0 = fma2(x0, wkv, ak0); ak1 = fma2(x1, wkv, ak1);
            av0 = fma2(x0, wvv, av0); av1 = fma2(x1, wvv, av1);
        }
        const float ibq = bq[co], ibk = bk[co], ibv = bv[co];
        float2 f;
        f = unpack2(aq0); sm[QSOFF + xi(lbase,co)]   = f.x + f.y + ibq;
        f = unpack2(aq1); sm[QSOFF + xi(lbase+1,co)] = f.x + f.y + ibq;
        f = unpack2(ak0); sm[KSOFF + xi(lbase,co)]   = f.x + f.y + ibk;
        f = unpack2(ak1); sm[KSOFF + xi(lbase+1,co)] = f.x + f.y + ibk;
        f = unpack2(av0); sm[VSOFF + xi(lbase,co)]   = f.x + f.y + ibv;
        f = unpack2(av1); sm[VSOFF + xi(lbase+1,co)] = f.x + f.y + ibv;
    }
    __syncthreads();

    // phase 3: attention (interleaved m = 4*mm + quarter); gate split 4-ways.
    {
        const int h = t >> 8, rem = t & 255;
        const int l = rem >> 2, quarter = rem & 3;
        const int hc = h*D_;
        const float rsd = 0.35355339059327373f;

        ulonglong2 qa = *reinterpret_cast<const ulonglong2*>(&sm[QSOFF + xi(l,hc)]);
        ulonglong2 qb = *reinterpret_cast<const ulonglong2*>(&sm[QSOFF + xi(l,hc+4)]);
        const u64 rsd2 = pack2(rsd, rsd);
        qa.x = mul2(qa.x, rsd2); qa.y = mul2(qa.y, rsd2);
        qb.x = mul2(qb.x, rsd2); qb.y = mul2(qb.y, rsd2);
        const float cw = conv_w[h], cb = conv_b[h];

        float Z = 0.f;
        u64 A0 = 0ull, A1 = 0ull, A2 = 0ull, A3 = 0ull;

        #pragma unroll 4
        for (int mm = 0; mm < 16; mm++) {
            const int m = mm*4 + quarter;
            const ulonglong2 ka = *reinterpret_cast<const ulonglong2*>(&sm[KSOFF + xi(m,hc)]);
            const ulonglong2 kb = *reinterpret_cast<const ulonglong2*>(&sm[KSOFF + xi(m,hc+4)]);
            u64 u = mul2(qa.x, ka.x);
            u = fma2(qa.y, ka.y, u);
            u = fma2(qb.x, kb.x, u);
            u = fma2(qb.y, kb.y, u);
            const float2 uf = unpack2(u);
            const float sc = uf.x + uf.y + fmaf(sm[BKI(l,m)], cw, cb);
            const float p = __expf(sc);
            Z += p;
            const u64 pp = pack2(p, p);
            const ulonglong2 va = *reinterpret_cast<const ulonglong2*>(&sm[VSOFF + xi(m,hc)]);
            const ulonglong2 vb = *reinterpret_cast<const ulonglong2*>(&sm[VSOFF + xi(m,hc+4)]);
            A0 = fma2(pp, va.x, A0); A1 = fma2(pp, va.y, A1);
            A2 = fma2(pp, vb.x, A2); A3 = fma2(pp, vb.y, A3);
        }
        #pragma unroll
        for (int o = 1; o < 4; o <<= 1) {
            Z  += __shfl_xor_sync(0xffffffffu, Z, o);
            A0 = add2(A0, __shfl_xor_sync(0xffffffffu, A0, o));
            A1 = add2(A1, __shfl_xor_sync(0xffffffffu, A1, o));
            A2 = add2(A2, __shfl_xor_sync(0xffffffffu, A2, o));
            A3 = add2(A3, __shfl_xor_sync(0xffffffffu, A3, o));
        }

        // every quarter computes 2 gate outputs (d = 2q, 2q+1)
        const float inv = 1.f/Z;
        const float2 f0 = unpack2(A0), f1 = unpack2(A1), f2 = unpack2(A2), f3 = unpack2(A3);
        float o[D_];
        o[0]=f0.x*inv; o[1]=f0.y*inv; o[2]=f1.x*inv; o[3]=f1.y*inv;
        o[4]=f2.x*inv; o[5]=f2.y*inv; o[6]=f3.x*inv; o[7]=f3.y*inv;
        const int d0 = quarter*2;
        float2 og;
        #pragma unroll
        for (int k = 0; k < 2; k++) {
            const int d = d0 + k;
            const float4 w0 = *reinterpret_cast<const float4*>(&sm[GWOFF + h*64 + d*8]);
            const float4 w1 = *reinterpret_cast<const float4*>(&sm[GWOFF + h*64 + d*8 + 4]);
            float g = sm[GBOFF + hc + d];
            g += w0.x*o[0] + w0.y*o[1] + w0.z*o[2] + w0.w*o[3];
            g += w1.x*o[4] + w1.y*o[5] + w1.z*o[6] + w1.w*o[7];
            (&og.x)[k] = __fdividef(o[d], 1.f + __expf(-g));
        }
        __syncthreads();                        // all q-reads of QS complete
        *reinterpret_cast<float2*>(&sm[QSOFF + xi(l, hc + d0)]) = og;
    }
    __syncthreads();

    // phase 4: wo + residual + LN(an) fused -> g_xbuf. warp -> 2 rows, lane=co.
    {
        const int co = t & 31, lbase = (t >> 5) * 2;
        const int x0b = lbase*18,     k0h = keyf(lbase)   >> 1;
        const int x1b = (lbase+1)*18, k1h = keyf(lbase+1) >> 1;
        const int wrow = co*17;
        u64 a0 = 0, a1 = 0;
        #pragma unroll 8
        for (int c2 = 0; c2 < 16; c2++) {
            const u64 w = smu[WO2U + wrow + c2];
            a0 = fma2(smu[(QSOFF>>1) + x0b + (c2 ^ k0h)], w, a0);
            a1 = fma2(smu[(QSOFF>>1) + x1b + (c2 ^ k1h)], w, a1);
        }
        const float ib = bo[co];
        const float2 fa = unpack2(a0), fb = unpack2(a1);
        const float v0 = sm[xi(lbase,co)]   + fa.x + fa.y + ib;
        const float v1 = sm[xi(lbase+1,co)] + fb.x + fb.y + ib;

        u64 S1 = pack2(v0, v1), S2 = pack2(v0*v0, v1*v1);
        #pragma unroll
        for (int o = 1; o < 32; o <<= 1) {
            S1 = add2(S1, __shfl_xor_sync(0xffffffffu, S1, o));
            S2 = add2(S2, __shfl_xor_sync(0xffffffffu, S2, o));
        }
        const float2 s1 = unpack2(S1), s2 = unpack2(S2);
        const float m0 = s1.x*(1.f/C_), m1 = s1.y*(1.f/C_);
        const float r0 = rsqrtf(s2.x*(1.f/C_) - m0*m0 + 1e-5f);
        const float r1 = rsqrtf(s2.y*(1.f/C_) - m1*m1 + 1e-5f);
        const float ag = an_g[co], ab = an_b[co];
        float* dst = g_xbuf + ((b*S_ + s)*L_ + lbase)*C_ + co;
        dst[0]   = (v0 - m0)*r0*ag + ab;
        dst[C_]  = (v1 - m1)*r1*ag + ab;
    }
}

// ---------------------------------------------------------------------------
// Kernel kWB: fused max/normalize/wi/pair-gemm/AdaNorm/SiLU.
// grid = (b, i-group-of-16) = 128 blocks, 512 threads. Dynamic smem:
//   msB@0 (64x36)  wiB@2304 (16 x 16x40 swzp)  pwS@12544 (16x1028 padded)
//   rinv@28992 (64)  total 29056 floats = 116224 B
// ---------------------------------------------------------------------------
#define MSB 0
#define WIB 2304
#define PWS 12544
#define RNV 28992
#define KWB_SMEM (29056*4)

__global__ void __launch_bounds__(512) kWB(
    const float* __restrict__ pp_w, const float* __restrict__ pp_b,
    const float* __restrict__ ada_g, const float* __restrict__ ada_b,
    const float* __restrict__ ada_alpha, float* __restrict__ out)
{
    extern __shared__ float smw[];
    const int t = threadIdx.x;
    const int b = blockIdx.x >> 2, i0 = (blockIdx.x & 3) * 16;
    const float* xb = g_xbuf + b*S_*L_*C_;

    // max over tracks -> msB (raw)
    for (int idx = t; idx < L_*C_; idx += 512) {
        const float m = fmaxf(fmaxf(xb[idx], xb[2048+idx]),
                              fmaxf(xb[4096+idx], xb[6144+idx]));
        smw[MSB + swz(idx>>5, idx&31)] = m;
    }
    // pp_w -> pwS (row stride 1028)
    for (int idx = t; idx < 4096; idx += 512) {
        const int p = idx >> 8, c4 = idx & 255;
        *reinterpret_cast<float4*>(&smw[PWS + p*1028 + c4*4]) =
            *reinterpret_cast<const float4*>(&pp_w[p*1024 + c4*4]);
    }
    __syncthreads();

    if (t < L_) {
        float ss = 0.f;
        #pragma unroll
        for (int c = 0; c < C_; c++) { const float v = smw[MSB + swz(t,c)]; ss += v*v; }
        smw[RNV + t] = rsqrtf(ss);
    }
    __syncthreads();
    for (int idx = t; idx < L_*C_; idx += 512) {
        const int r = idx >> 5;
        smw[MSB + swz(r, idx&31)] *= smw[RNV + r];
    }
    __syncthreads();

    // wi phase: warp = ii (local i), lane -> (ph, dq). ŵ = m̂_i^T W_p.
    {
        const int ii = t >> 5, lane = t & 31;
        const int ph = lane >> 2, d0 = (lane & 3) * 8;
        u64 acc[2][4];
        #pragma unroll
        for (int pk = 0; pk < 2; pk++)
            #pragma unroll
            for (int k = 0; k < 4; k++) acc[pk][k] = 0ull;
        #pragma unroll 8
        for (int c = 0; c < C_; c++) {
            const float mc = smw[MSB + swz(i0+ii, c)];   // warp broadcast
            const u64 m2 = pack2(mc, mc);
            #pragma unroll
            for (int pk = 0; pk < 2; pk++) {
                const int p = ph + 8*pk;
                const ulonglong2 w0 = *reinterpret_cast<const ulonglong2*>(&smw[PWS + p*1028 + c*32 + d0]);
                const ulonglong2 w1 = *reinterpret_cast<const ulonglong2*>(&smw[PWS + p*1028 + c*32 + d0 + 4]);
                acc[pk][0] = fma2(m2, w0.x, acc[pk][0]);
                acc[pk][1] = fma2(m2, w0.y, acc[pk][1]);
                acc[pk][2] = fma2(m2, w1.x, acc[pk][2]);
                acc[pk][3] = fma2(m2, w1.y, acc[pk][3]);
            }
        }
        #pragma unroll
        for (int pk = 0; pk < 2; pk++) {
            const int p = ph + 8*pk;
            ulonglong2 s0; s0.x = acc[pk][0]; s0.y = acc[pk][1];
            ulonglong2 s1; s1.x = acc[pk][2]; s1.y = acc[pk][3];
            *reinterpret_cast<ulonglong2*>(&smw[WIB + ii*640 + swzp(p, d0)])   = s0;
            *reinterpret_cast<ulonglong2*>(&smw[WIB + ii*640 + swzp(p, d0+4)]) = s1;
        }
    }
    __syncthreads();

    // pair gemm + AdaNorm + SiLU. 2 passes x (2 ii x 2 p x 4 j) per thread.
    const int iig = t >> 7, sub = t & 127;
    const int jg = sub >> 3, j0 = jg*4, pq = sub & 7;
    const float alpha = ada_alpha[0];
    const float bp0 = pp_b[pq],  bp1 = pp_b[pq+8];
    const float ag0 = ada_g[pq], ag1 = ada_g[pq+8];
    const float ab0 = ada_b[pq], ab1 = ada_b[pq+8];

    #pragma unroll
    for (int pass = 0; pass < 2; pass++) {
        u64 acc[2][2][4];
        #pragma unroll
        for (int a = 0; a < 2; a++)
            #pragma unroll
            for (int pk = 0; pk < 2; pk++)
                #pragma unroll
                for (int jk = 0; jk < 4; jk++) acc[a][pk][jk] = 0ull;

        #pragma unroll
        for (int ch = 0; ch < 8; ch++) {
            const int cd = ch*4;
            ulonglong2 mj[4];
            #pragma unroll
            for (int jk = 0; jk < 4; jk++)
                mj[jk] = *reinterpret_cast<const ulonglong2*>(&smw[MSB + swz(j0+jk, cd)]);
            #pragma unroll
            for (int a = 0; a < 2; a++) {
                const int ii = iig*2 + a + 8*pass;
                #pragma unroll
                for (int pk = 0; pk < 2; pk++) {
                    const ulonglong2 wp = *reinterpret_cast<const ulonglong2*>(
                        &smw[WIB + ii*640 + swzp(pq + 8*pk, cd)]);
                    #pragma unroll
                    for (int jk = 0; jk < 4; jk++) {
                        acc[a][pk][jk] = fma2(wp.x, mj[jk].x, acc[a][pk][jk]);
                        acc[a][pk][jk] = fma2(wp.y, mj[jk].y, acc[a][pk][jk]);
                    }
                }
            }
        }

        float feat[2][2][4];
        #pragma unroll
        for (int a = 0; a < 2; a++)
            #pragma unroll
            for (int pk = 0; pk < 2; pk++) {
                const float bp = pk ? bp1 : bp0;
                #pragma unroll
                for (int jk = 0; jk < 4; jk++) {
                    const float2 f = unpack2(acc[a][pk][jk]);
                    feat[a][pk][jk] = f.x + f.y + bp;
                }
            }

        // AdaNorm stats over 16 p: local pair + shfl over 8 pq lanes, both ii packed
        u64 S1[4], S2[4];
        #pragma unroll
        for (int jk = 0; jk < 4; jk++) {
            S1[jk] = pack2(feat[0][0][jk] + feat[0][1][jk],
                           feat[1][0][jk] + feat[1][1][jk]);
            S2[jk] = pack2(feat[0][0][jk]*feat[0][0][jk] + feat[0][1][jk]*feat[0][1][jk],
                           feat[1][0][jk]*feat[1][0][jk] + feat[1][1][jk]*feat[1][1][jk]);
        }
        #pragma unroll
        for (int o = 1; o < 8; o <<= 1)
            #pragma unroll
            for (int jk = 0; jk < 4; jk++) {
                S1[jk] = add2(S1[jk], __shfl_xor_sync(0xffffffffu, S1[jk], o));
                S2[jk] = add2(S2[jk], __shfl_xor_sync(0xffffffffu, S2[jk], o));
            }
        float mu[2][4], rsd[2][4];
        #pragma unroll
        for (int jk = 0; jk < 4; jk++) {
            const float2 s1 = unpack2(S1[jk]), s2 = unpack2(S2[jk]);
            mu[0][jk] = s1.x*(1.f/CP_);
            mu[1][jk] = s1.y*(1.f/CP_);
            rsd[0][jk] = rsqrtf(s2.x*(1.f/CP_) - mu[0][jk]*mu[0][jk] + 1e-5f);
            rsd[1][jk] = rsqrtf(s2.y*(1.f/CP_) - mu[1][jk]*mu[1][jk] + 1e-5f);
        }

        #pragma unroll
        for (int a = 0; a < 2; a++) {
            const int i = i0 + iig*2 + a + 8*pass;
            #pragma unroll
            for (int pk = 0; pk < 2; pk++) {
                const int p = pq + 8*pk;
                const float g = pk ? ag1 : ag0, bb = pk ? ab1 : ab0;
                float4 r;
                #pragma unroll
                for (int jk = 0; jk < 4; jk++) {
                    const float v = feat[a][pk][jk];
                    const float ln = (v - mu[a][jk])*rsd[a][jk]*g + bb;
                    const float val = v + alpha*ln;
                    (&r.x)[jk] = __fdividef(val, 1.f + __expf(-val));
                }
                *reinterpret_cast<float4*>(&out[((b*CP_ + p)*L_ + i)*L_ + j0]) = r;
            }
        }
    }
}

extern "C" void kernel_launch(void* const* d_in, const int* in_sizes, int n_in,
                              void* d_out, int out_size) {
    const float* in[29];
    for (int i = 0; i < 29 && i < n_in; i++) in[i] = (const float*)d_in[i];

    cudaFuncSetAttribute(kA,  cudaFuncAttributeMaxDynamicSharedMemorySize, KA_SMEM);
    cudaFuncSetAttribute(kWB, cudaFuncAttributeMaxDynamicSharedMemorySize, KWB_SMEM);

    kA<<<B_*S_, 1024, KA_SMEM>>>(in[0], in[1], in[2], in[3], in[4],
                                 in[5], in[6], in[7], in[8], in[9],
                                 in[10], in[11], in[12], in[13], in[14], in[15],
                                 in[16], in[17], in[18], in[19],
                                 in[20], in[21], in[22], in[23]);
    kWB<<<B_*4, 512, KWB_SMEM>>>(in[24], in[25], in[26], in[27], in[28],
                                 (float*)d_out);
}